// round 2
// baseline (speedup 1.0000x reference)
#include <cuda_runtime.h>

// DiarizationLoss: B=32, T=65536, S=4, scalar output.
// Inputs (metadata order): pred_speakers f32[B,T,S], pred_vad f32[B,T],
//                          labels f32[B,T,S], vad f32[B,T], lengths (i32 or i64)[B]
// out: f32[1]

#define NB 32
#define NT 65536
#define NS 4
#define CEPS 1e-7f

#define CHUNKS 64           // chunks per batch
#define THREADS 256
#define CHUNK_T (NT / CHUNKS)   // 1024 -> 4 iters/thread

// per-batch partials: [0..15] sum (lp-lq)_i * label_j  (i*4+j)
//                     [16..19] sum lq_i
//                     [20]     vad bce sum
__device__ float g_part[NB][21];

// lengths dtype probe: values are in [32768, 65536), all nonzero.
// int64 LE layout => word 1 (high word of lengths[0]) == 0.
// int32 layout    => word 1 == lengths[1] >= 32768 != 0.
__device__ __forceinline__ int load_len(const int* __restrict__ p32, int b) {
    return (p32[1] == 0) ? p32[2 * b] : p32[b];
}

__global__ void zero_kernel() {
    int i = blockIdx.x * blockDim.x + threadIdx.x;
    if (i < NB * 21) ((float*)g_part)[i] = 0.0f;
}

__global__ __launch_bounds__(THREADS) void reduce_kernel(
    const float* __restrict__ ps,      // [B,T,S]
    const float* __restrict__ pv,      // [B,T]
    const float* __restrict__ lb,      // [B,T,S]
    const float* __restrict__ vad,     // [B,T]
    const int* __restrict__ len32)
{
    const int b     = blockIdx.x / CHUNKS;
    const int chunk = blockIdx.x % CHUNKS;
    const int len   = load_len(len32, b);
    const int t0    = chunk * CHUNK_T;

    if (t0 >= len) return;   // whole block masked out (uniform, safe)

    float acc[21];
    #pragma unroll
    for (int k = 0; k < 21; k++) acc[k] = 0.0f;

    const int tend = min(t0 + CHUNK_T, len);
    const float4* __restrict__ psb = (const float4*)(ps + (size_t)b * NT * NS);
    const float4* __restrict__ lbb = (const float4*)(lb + (size_t)b * NT * NS);
    const float*  __restrict__ pvb = pv  + (size_t)b * NT;
    const float*  __restrict__ vb  = vad + (size_t)b * NT;

    for (int t = t0 + threadIdx.x; t < tend; t += THREADS) {
        float4 p4 = psb[t];
        float4 l4 = lbb[t];
        float pp[4] = {p4.x, p4.y, p4.z, p4.w};
        float ll[4] = {l4.x, l4.y, l4.z, l4.w};
        float d[4];
        #pragma unroll
        for (int i = 0; i < 4; i++) {
            float p  = fminf(fmaxf(pp[i], CEPS), 1.0f - CEPS);
            float lq = __logf(1.0f - p);
            float lp = __logf(p);
            d[i] = lp - lq;
            acc[16 + i] += lq;
        }
        #pragma unroll
        for (int i = 0; i < 4; i++)
            #pragma unroll
            for (int j = 0; j < 4; j++)
                acc[i * 4 + j] += d[i] * ll[j];

        // VAD BCE: label v in {0,1} -> bce = -log(v ? pv : 1-pv)
        float pvv = fminf(fmaxf(pvb[t], CEPS), 1.0f - CEPS);
        float v   = vb[t];
        float arg = (v > 0.5f) ? pvv : (1.0f - pvv);
        acc[20] -= __logf(arg);
    }

    // block reduction: warp shuffle -> shared -> one RED per value
    __shared__ float sm[21][8];
    const int lane = threadIdx.x & 31;
    const int w    = threadIdx.x >> 5;
    #pragma unroll
    for (int k = 0; k < 21; k++) {
        float v = acc[k];
        v += __shfl_down_sync(0xffffffffu, v, 16);
        v += __shfl_down_sync(0xffffffffu, v, 8);
        v += __shfl_down_sync(0xffffffffu, v, 4);
        v += __shfl_down_sync(0xffffffffu, v, 2);
        v += __shfl_down_sync(0xffffffffu, v, 1);
        if (lane == 0) sm[k][w] = v;
    }
    __syncthreads();
    if (threadIdx.x < 21) {
        float v = 0.0f;
        #pragma unroll
        for (int ww = 0; ww < 8; ww++) v += sm[threadIdx.x][ww];
        atomicAdd(&g_part[b][threadIdx.x], v);
    }
}

__global__ void finalize_kernel(const int* __restrict__ len32,
                                float* __restrict__ out)
{
    const int b = threadIdx.x;   // 32 threads, one batch each
    const float msum = (float)load_len(len32, b);
    const float inv  = 1.0f / msum;

    float L[4][4];
    #pragma unroll
    for (int i = 0; i < 4; i++)
        #pragma unroll
        for (int j = 0; j < 4; j++)
            L[i][j] = -(g_part[b][i * 4 + j] + g_part[b][16 + i]) * inv;

    // exhaustive S=4 permutation min
    float best = 3.4e38f;
    #pragma unroll
    for (int a = 0; a < 4; a++)
        #pragma unroll
        for (int c = 0; c < 4; c++) {
            if (c == a) continue;
            #pragma unroll
            for (int e = 0; e < 4; e++) {
                if (e == a || e == c) continue;
                int f = 6 - a - c - e;
                float s = L[0][a] + L[1][c] + L[2][e] + L[3][f];
                best = fminf(best, s);
            }
        }
    best *= 0.25f;

    float vs = g_part[b][20];
    float sb = best, sv = vs, sd = msum;
    #pragma unroll
    for (int off = 16; off >= 1; off >>= 1) {
        sb += __shfl_xor_sync(0xffffffffu, sb, off);
        sv += __shfl_xor_sync(0xffffffffu, sv, off);
        sd += __shfl_xor_sync(0xffffffffu, sd, off);
    }
    if (b == 0)
        out[0] = (sb / (float)NB) + 0.5f * (sv / sd);
}

extern "C" void kernel_launch(void* const* d_in, const int* in_sizes, int n_in,
                              void* d_out, int out_size)
{
    const float* ps  = (const float*)d_in[0];
    const float* pv  = (const float*)d_in[1];
    const float* lb  = (const float*)d_in[2];
    const float* vad = (const float*)d_in[3];
    const int*   len = (const int*)d_in[4];
    float* out = (float*)d_out;

    zero_kernel<<<3, 256>>>();
    reduce_kernel<<<NB * CHUNKS, THREADS>>>(ps, pv, lb, vad, len);
    finalize_kernel<<<1, 32>>>(len, out);
}

// round 3
// speedup vs baseline: 1.0555x; 1.0555x over previous
#include <cuda_runtime.h>

// DiarizationLoss: B=32, T=65536, S=4, scalar output. Single fused kernel.
// Inputs: pred_speakers f32[B,T,S], pred_vad f32[B,T], labels f32[B,T,S],
//         vad f32[B,T], lengths (i32 or i64)[B].  out: f32[1]

#define NB 32
#define NT 65536
#define CEPS 1e-7f

#define CHUNKS 64
#define THREADS 256
#define CHUNK_T (NT / CHUNKS)   // 1024 -> 4 iters/thread
#define GRID (NB * CHUNKS)      // 2048 blocks

// per-batch partials: [0..15] sum (lp-lq)_i * label_j  (i*4+j)
//                     [16..19] sum lq_i ; [20] vad bce sum
__device__ float g_part[NB][21];          // zero-initialized at load; each run re-zeroes
__device__ unsigned int g_count;          // ditto

// lengths dtype probe: values in [32768,65536), nonzero.
// int64 LE => word1 (hi of lengths[0]) == 0 ; int32 => word1 >= 32768.
__device__ __forceinline__ int load_len(const int* __restrict__ p32, int b) {
    return (p32[1] == 0) ? p32[2 * b] : p32[b];
}

__global__ __launch_bounds__(THREADS) void diar_loss_kernel(
    const float* __restrict__ ps,
    const float* __restrict__ pv,
    const float* __restrict__ lb,
    const float* __restrict__ vad,
    const int*   __restrict__ len32,
    float*       __restrict__ out)
{
    const int b     = blockIdx.x / CHUNKS;
    const int chunk = blockIdx.x % CHUNKS;
    const int len   = load_len(len32, b);
    const int t0    = chunk * CHUNK_T;
    const bool did_work = (t0 < len);   // block-uniform

    if (did_work) {
        float acc[21];
        #pragma unroll
        for (int k = 0; k < 21; k++) acc[k] = 0.0f;

        const float4* __restrict__ psb = (const float4*)(ps + (size_t)b * NT * 4);
        const float4* __restrict__ lbb = (const float4*)(lb + (size_t)b * NT * 4);
        const float*  __restrict__ pvb = pv  + (size_t)b * NT;
        const float*  __restrict__ vb  = vad + (size_t)b * NT;

        auto body = [&](int t) {
            float4 p4 = psb[t];
            float4 l4 = lbb[t];
            float pvv = pvb[t];
            float v   = vb[t];
            float pp[4] = {p4.x, p4.y, p4.z, p4.w};
            float ll[4] = {l4.x, l4.y, l4.z, l4.w};
            float d[4];
            #pragma unroll
            for (int i = 0; i < 4; i++) {
                float p  = fminf(fmaxf(pp[i], CEPS), 1.0f - CEPS);
                float lq = __logf(1.0f - p);
                float lp = __logf(p);
                d[i] = lp - lq;
                acc[16 + i] += lq;
            }
            #pragma unroll
            for (int i = 0; i < 4; i++)
                #pragma unroll
                for (int j = 0; j < 4; j++)
                    acc[i * 4 + j] += d[i] * ll[j];
            pvv = fminf(fmaxf(pvv, CEPS), 1.0f - CEPS);
            float arg = (v > 0.5f) ? pvv : (1.0f - pvv);
            acc[20] -= __logf(arg);
        };

        if (t0 + CHUNK_T <= len) {          // full chunk: unrolled, max MLP
            int t = t0 + threadIdx.x;
            #pragma unroll
            for (int it = 0; it < CHUNK_T / THREADS; it++, t += THREADS)
                body(t);
        } else {                             // boundary chunk
            for (int t = t0 + threadIdx.x; t < len; t += THREADS)
                body(t);
        }

        // block reduction: warp shuffle -> shared -> one RED per value
        __shared__ float sm[21][8];
        const int lane = threadIdx.x & 31;
        const int w    = threadIdx.x >> 5;
        #pragma unroll
        for (int k = 0; k < 21; k++) {
            float v = acc[k];
            v += __shfl_down_sync(0xffffffffu, v, 16);
            v += __shfl_down_sync(0xffffffffu, v, 8);
            v += __shfl_down_sync(0xffffffffu, v, 4);
            v += __shfl_down_sync(0xffffffffu, v, 2);
            v += __shfl_down_sync(0xffffffffu, v, 1);
            if (lane == 0) sm[k][w] = v;
        }
        __syncthreads();
        if (threadIdx.x < 21) {
            float v = 0.0f;
            #pragma unroll
            for (int ww = 0; ww < 8; ww++) v += sm[threadIdx.x][ww];
            atomicAdd(&g_part[b][threadIdx.x], v);
        }
    }

    // ---- last-block finalize ----
    __shared__ int s_last;
    if (threadIdx.x == 0) {
        __threadfence();
        unsigned prev = atomicAdd(&g_count, 1u);
        s_last = (prev == (unsigned)(GRID - 1));
    }
    __syncthreads();
    if (!s_last) return;
    __threadfence();

    if (threadIdx.x < NB) {
        const int bb = threadIdx.x;
        const float msum = (float)load_len(len32, bb);
        const float inv  = 1.0f / msum;

        float L[4][4];
        #pragma unroll
        for (int i = 0; i < 4; i++)
            #pragma unroll
            for (int j = 0; j < 4; j++)
                L[i][j] = -(g_part[bb][i * 4 + j] + g_part[bb][16 + i]) * inv;

        float best = 3.4e38f;
        #pragma unroll
        for (int a = 0; a < 4; a++)
            #pragma unroll
            for (int c = 0; c < 4; c++) {
                if (c == a) continue;
                #pragma unroll
                for (int e = 0; e < 4; e++) {
                    if (e == a || e == c) continue;
                    int f = 6 - a - c - e;
                    best = fminf(best, L[0][a] + L[1][c] + L[2][e] + L[3][f]);
                }
            }
        best *= 0.25f;

        float sb = best, sv = g_part[bb][20], sd = msum;
        #pragma unroll
        for (int off = 16; off >= 1; off >>= 1) {
            sb += __shfl_xor_sync(0xffffffffu, sb, off);
            sv += __shfl_xor_sync(0xffffffffu, sv, off);
            sd += __shfl_xor_sync(0xffffffffu, sd, off);
        }
        if (bb == 0)
            out[0] = (sb / (float)NB) + 0.5f * (sv / sd);
    }
    __syncthreads();

    // reset scratch for the next graph replay (deterministic state)
    for (int i = threadIdx.x; i < NB * 21; i += THREADS)
        ((float*)g_part)[i] = 0.0f;
    if (threadIdx.x == 0) g_count = 0u;
}

extern "C" void kernel_launch(void* const* d_in, const int* in_sizes, int n_in,
                              void* d_out, int out_size)
{
    const float* ps  = (const float*)d_in[0];
    const float* pv  = (const float*)d_in[1];
    const float* lb  = (const float*)d_in[2];
    const float* vad = (const float*)d_in[3];
    const int*   len = (const int*)d_in[4];
    float* out = (float*)d_out;

    diar_loss_kernel<<<GRID, THREADS>>>(ps, pv, lb, vad, len, out);
}

// round 4
// speedup vs baseline: 1.1195x; 1.0607x over previous
#include <cuda_runtime.h>

// DiarizationLoss: B=32, T=65536, S=4, scalar output. Single fused kernel.

#define NB 32
#define NT 65536
#define CEPS 1e-7f

#define CHUNKS 32
#define THREADS 256
#define CHUNK_T (NT / CHUNKS)          // 2048
#define ITERS  (CHUNK_T / THREADS)     // 8
#define GRID (NB * CHUNKS)             // 1024 blocks

__device__ float g_part[NB][21];
__device__ unsigned int g_count;

// lengths dtype probe: values in [32768,65536), nonzero.
// int64 LE => word1 (hi of lengths[0]) == 0 ; int32 => word1 >= 32768.
__device__ __forceinline__ int load_len(const int* __restrict__ p32, int b) {
    return (p32[1] == 0) ? p32[2 * b] : p32[b];
}

__global__ __launch_bounds__(THREADS) void diar_loss_kernel(
    const float* __restrict__ ps,
    const float* __restrict__ pv,
    const float* __restrict__ lb,
    const float* __restrict__ vad,
    const int*   __restrict__ len32,
    float*       __restrict__ out)
{
    const int b     = blockIdx.x / CHUNKS;
    const int chunk = blockIdx.x % CHUNKS;
    const int len   = load_len(len32, b);
    const int t0    = chunk * CHUNK_T;
    const bool did_work = (t0 < len);   // block-uniform

    if (did_work) {
        float acc[21];
        #pragma unroll
        for (int k = 0; k < 21; k++) acc[k] = 0.0f;

        const float4* __restrict__ psb = (const float4*)(ps + (size_t)b * NT * 4);
        const float4* __restrict__ lbb = (const float4*)(lb + (size_t)b * NT * 4);
        const float*  __restrict__ pvb = pv  + (size_t)b * NT;
        const float*  __restrict__ vb  = vad + (size_t)b * NT;

        auto compute = [&](float4 p4, float4 l4, float pvv, float v) {
            float pp[4] = {p4.x, p4.y, p4.z, p4.w};
            float ll[4] = {l4.x, l4.y, l4.z, l4.w};
            float d[4];
            #pragma unroll
            for (int i = 0; i < 4; i++) {
                float p  = fminf(fmaxf(pp[i], CEPS), 1.0f - CEPS);
                float lq = __logf(1.0f - p);
                float lp = __logf(p);
                d[i] = lp - lq;
                acc[16 + i] += lq;
            }
            #pragma unroll
            for (int i = 0; i < 4; i++)
                #pragma unroll
                for (int j = 0; j < 4; j++)
                    acc[i * 4 + j] += d[i] * ll[j];
            pvv = fminf(fmaxf(pvv, CEPS), 1.0f - CEPS);
            float arg = (v > 0.5f) ? pvv : (1.0f - pvv);
            acc[20] -= __logf(arg);
        };

        if (t0 + CHUNK_T <= len) {
            // full chunk: software-pipelined (double-buffered loads)
            int t = t0 + threadIdx.x;
            float4 pc = psb[t], lc = lbb[t];
            float pvc = pvb[t], vc = vb[t];
            #pragma unroll
            for (int it = 0; it < ITERS; it++) {
                float4 pn, ln; float pvn, vn;
                if (it + 1 < ITERS) {
                    int tn = t + THREADS;
                    pn = psb[tn]; ln = lbb[tn];
                    pvn = pvb[tn]; vn = vb[tn];
                }
                compute(pc, lc, pvc, vc);
                pc = pn; lc = ln; pvc = pvn; vc = vn;
                t += THREADS;
            }
        } else {
            for (int t = t0 + threadIdx.x; t < len; t += THREADS)
                compute(psb[t], lbb[t], pvb[t], vb[t]);
        }

        // block reduction: warp shuffle -> shared -> one RED per value
        __shared__ float sm[21][8];
        const int lane = threadIdx.x & 31;
        const int w    = threadIdx.x >> 5;
        #pragma unroll
        for (int k = 0; k < 21; k++) {
            float v = acc[k];
            v += __shfl_down_sync(0xffffffffu, v, 16);
            v += __shfl_down_sync(0xffffffffu, v, 8);
            v += __shfl_down_sync(0xffffffffu, v, 4);
            v += __shfl_down_sync(0xffffffffu, v, 2);
            v += __shfl_down_sync(0xffffffffu, v, 1);
            if (lane == 0) sm[k][w] = v;
        }
        __syncthreads();
        if (threadIdx.x < 21) {
            float v = 0.0f;
            #pragma unroll
            for (int ww = 0; ww < 8; ww++) v += sm[threadIdx.x][ww];
            atomicAdd(&g_part[b][threadIdx.x], v);
        }
    }

    // ---- last-block finalize ----
    __shared__ int s_last;
    if (threadIdx.x == 0) {
        __threadfence();
        unsigned prev = atomicAdd(&g_count, 1u);
        s_last = (prev == (unsigned)(GRID - 1));
    }
    __syncthreads();
    if (!s_last) return;
    __threadfence();

    if (threadIdx.x < NB) {
        const int bb = threadIdx.x;
        const float msum = (float)load_len(len32, bb);
        const float inv  = 1.0f / msum;

        float L[4][4];
        #pragma unroll
        for (int i = 0; i < 4; i++)
            #pragma unroll
            for (int j = 0; j < 4; j++)
                L[i][j] = -(g_part[bb][i * 4 + j] + g_part[bb][16 + i]) * inv;

        float best = 3.4e38f;
        #pragma unroll
        for (int a = 0; a < 4; a++)
            #pragma unroll
            for (int c = 0; c < 4; c++) {
                if (c == a) continue;
                #pragma unroll
                for (int e = 0; e < 4; e++) {
                    if (e == a || e == c) continue;
                    int f = 6 - a - c - e;
                    best = fminf(best, L[0][a] + L[1][c] + L[2][e] + L[3][f]);
                }
            }
        best *= 0.25f;

        float sb = best, sv = g_part[bb][20], sd = msum;
        #pragma unroll
        for (int off = 16; off >= 1; off >>= 1) {
            sb += __shfl_xor_sync(0xffffffffu, sb, off);
            sv += __shfl_xor_sync(0xffffffffu, sv, off);
            sd += __shfl_xor_sync(0xffffffffu, sd, off);
        }
        if (bb == 0)
            out[0] = (sb / (float)NB) + 0.5f * (sv / sd);
    }
    __syncthreads();

    // reset scratch for next graph replay
    for (int i = threadIdx.x; i < NB * 21; i += THREADS)
        ((float*)g_part)[i] = 0.0f;
    if (threadIdx.x == 0) g_count = 0u;
}

extern "C" void kernel_launch(void* const* d_in, const int* in_sizes, int n_in,
                              void* d_out, int out_size)
{
    diar_loss_kernel<<<GRID, THREADS>>>(
        (const float*)d_in[0], (const float*)d_in[1],
        (const float*)d_in[2], (const float*)d_in[3],
        (const int*)d_in[4], (float*)d_out);
}